// round 5
// baseline (speedup 1.0000x reference)
#include <cuda_runtime.h>
#include <cstdint>

#define B_ 64
#define Q_ 900
#define T_ 100
#define C_ 256
#define NTC 256          // cost kernel block
#define NTH 128          // hungarian block
#define K_ 8             // columns per hungarian thread: NTH*K_ >= Q_
#define NW (NTH / 32)

// Scratch: transposed cost [B, T, Q] so hungarian reads contiguous rows.
__device__ float g_costT[(size_t)B_ * T_ * Q_];
// Per-(b,t) ~packed row-min key; 0 (static init) is the identity for atomicMax.
// real key = ~stored;  key = (order(cost) << 32) | q  -> max(~key) == min(key)
__device__ unsigned long long g_rowmin[B_ * T_];   // zero-initialized

__device__ __forceinline__ unsigned order_f(float f) {
    unsigned o = __float_as_uint(f);
    return (o & 0x80000000u) ? ~o : (o | 0x80000000u);
}
__device__ __forceinline__ float unorder_f(unsigned o) {
    return __uint_as_float((o & 0x80000000u) ? (o ^ 0x80000000u) : ~o);
}

// ---------------------------------------------------------------------------
// Kernel 1: one block per (b, 32-query tile). Label-sorted target order makes
// the logits gather semi-coalesced. Writes out[B,Q,T] and g_costT[B,T,Q]
// coalesced from the smem tile; folds per-target row-min into g_rowmin.
// ---------------------------------------------------------------------------
__global__ void __launch_bounds__(NTC) cost_fused_kernel(
        const float* __restrict__ logits,
        const float* __restrict__ pboxes,
        const int* __restrict__ labels,
        const float* __restrict__ tboxes,
        float* __restrict__ out) {
    __shared__ int    lab_s[T_];
    __shared__ int    ord_s[T_];      // targets sorted by (label, t)
    __shared__ float4 tb_s[T_];
    __shared__ float4 pb_s[32];
    __shared__ float  tile[32][101];  // [q_in_tile][t]

    int b = blockIdx.y;
    int q0 = blockIdx.x * 32;
    int tid = threadIdx.x;

    if (tid < T_) {
        int lab = labels[b * T_ + tid];
        lab_s[tid] = lab;
        tb_s[tid] = __ldg(&((const float4*)tboxes)[b * T_ + tid]);
    }
    if (tid < 32 && q0 + tid < Q_)
        pb_s[tid] = __ldg(&((const float4*)pboxes)[b * Q_ + q0 + tid]);
    __syncthreads();

    if (tid < T_) {                   // rank sort by (label, index)
        int lab = lab_s[tid];
        int rank = 0;
        for (int s = 0; s < T_; s++) {
            int ls = lab_s[s];
            rank += (ls < lab) || (ls == lab && s < tid);
        }
        ord_s[rank] = tid;
    }
    __syncthreads();

    int qq = tid >> 3;                // 0..31
    int q = q0 + qq;
    int t_lo = tid & 7;               // 0..7
    if (q < Q_) {
        float4 pb = pb_s[qq];
        float ax0 = pb.x - 0.5f * pb.z, ay0 = pb.y - 0.5f * pb.w;
        float ax1 = pb.x + 0.5f * pb.z, ay1 = pb.y + 0.5f * pb.w;
        float areaA = (ax1 - ax0) * (ay1 - ay0);
        const float* lrow = logits + ((long long)b * Q_ + q) * C_;

        #pragma unroll
        for (int s = 0; s < 13; s++) {
            int sidx = t_lo + (s << 3);
            if (sidx >= T_) break;
            int tt = ord_s[sidx];     // label-sorted order -> coalesced gather

            float cc = -__ldg(lrow + lab_s[tt]);
            float4 tb = tb_s[tt];

            float cb = fabsf(pb.x - tb.x) + fabsf(pb.y - tb.y);
            cb += fabsf(pb.z - tb.z);
            cb += fabsf(pb.w - tb.w);

            float bx0 = tb.x - 0.5f * tb.z, by0 = tb.y - 0.5f * tb.w;
            float bx1 = tb.x + 0.5f * tb.z, by1 = tb.y + 0.5f * tb.w;

            float areaB = (bx1 - bx0) * (by1 - by0);
            float wx = fminf(ax1, bx1) - fmaxf(ax0, bx0); wx = fmaxf(wx, 0.f);
            float wy = fminf(ay1, by1) - fmaxf(ay0, by0); wy = fmaxf(wy, 0.f);
            float inter = wx * wy;
            float uni = areaA + areaB - inter;
            float iou = inter / uni;
            float ex = fmaxf(ax1, bx1) - fminf(ax0, bx0); ex = fmaxf(ex, 0.f);
            float ey = fmaxf(ay1, by1) - fminf(ay0, by0); ey = fmaxf(ey, 0.f);
            float enc = ex * ey;
            float giou = iou - (enc - uni) / enc;

            tile[qq][tt] = (cc + cb) - giou;
        }
    }
    __syncthreads();

    // out[B,Q,T]: coalesced (t fast) from smem
    for (int idx = tid; idx < 32 * T_; idx += NTC) {
        int qq2 = idx / T_, tt = idx - qq2 * T_;
        int q2 = q0 + qq2;
        if (q2 < Q_)
            out[((size_t)b * Q_ + q2) * T_ + tt] = tile[qq2][tt];
    }
    // costT[B,T,Q]: coalesced (q fast)
    for (int idx = tid; idx < 32 * T_; idx += NTC) {
        int tt = idx >> 5, q2 = q0 + (idx & 31);
        if (q2 < Q_)
            g_costT[((size_t)b * T_ + tt) * Q_ + q2] = tile[idx & 31][tt];
    }
    // per-target min over this block's queries -> atomicMax of ~key
    if (tid < T_) {
        unsigned long long best = ~0ull;
        int qmax = min(32, Q_ - q0);
        for (int k = 0; k < qmax; k++) {
            unsigned long long key =
                ((unsigned long long)order_f(tile[k][tid]) << 32) | (unsigned)(q0 + k);
            if (key < best) best = key;
        }
        atomicMax(&g_rowmin[b * T_ + tid], ~best);
    }
}

// ---------------------------------------------------------------------------
// Kernel 2: JV, greedy init from precomputed row-mins + deferred-dual SAP.
// One CTA (128 threads) per batch. Resets g_rowmin to 0 at the end.
// ---------------------------------------------------------------------------
__global__ void __launch_bounds__(NTH) hungarian_kernel(float* __restrict__ out,
                                                        int writeIdx) {
    int b = blockIdx.x;
    const float* cost = g_costT + (size_t)b * T_ * Q_;

    __shared__ float u[T_ + 1];
    __shared__ int p[Q_];                 // row matched to col j (-1 free)
    __shared__ int sway[Q_];              // predecessor column
    __shared__ unsigned long long wred[2][NW];
    __shared__ int colarr[T_];
    __shared__ int argj[T_];
    __shared__ int matched[T_];

    int tid = threadIdx.x;
    int lane = tid & 31, wid = tid >> 5;

    float vreg[K_];
    float minv[K_];
    #pragma unroll
    for (int k = 0; k < K_; k++) vreg[k] = 0.f;

    for (int j = tid; j < Q_; j += NTH) p[j] = -1;
    if (tid == 0) u[T_] = 0.f;

    // ---- Phase 0: greedy duals from precomputed row-mins ----
    if (tid < T_) {
        unsigned long long key = ~g_rowmin[b * T_ + tid];
        argj[tid] = (int)(key & 0xFFFFFFFFu);
        u[tid] = unorder_f((unsigned)(key >> 32));
    }
    __syncthreads();

    if (tid == 0) {
        for (int i = 0; i < T_; i++) {
            int j = argj[i];
            if (p[j] < 0) { p[j] = i; matched[i] = 1; }
            else matched[i] = 0;
        }
    }
    __syncthreads();

    // ---- Phase 1: shortest augmenting path for each unmatched row ----
    for (int i = 0; i < T_; i++) {
        if (matched[i]) continue;

        unsigned um = 0;
        #pragma unroll
        for (int k = 0; k < K_; k++) {
            minv[k] = 1e30f;
            if (tid + k * NTH >= Q_) um |= (1u << k);
        }

        int j0 = Q_;
        int i0 = i;
        float shift = 0.f;
        int iter = 0;
        int j1;
        float Sf;

        while (true) {
            float base = shift - u[i0];
            const float* row = cost + (size_t)i0 * Q_;

            unsigned long long best = ~0ull;
            #pragma unroll
            for (int k = 0; k < K_; k++) {
                int j = tid + k * NTH;
                if (!((um >> k) & 1u)) {
                    float cur = __ldg(row + j) - vreg[k] + base;
                    if (cur < minv[k]) { minv[k] = cur; sway[j] = j0; }
                    unsigned long long key =
                        ((unsigned long long)order_f(minv[k]) << 32) | (unsigned)j;
                    if (key < best) best = key;
                }
            }
            #pragma unroll
            for (int off = 16; off; off >>= 1) {
                unsigned long long oth = __shfl_xor_sync(0xFFFFFFFFu, best, off);
                if (oth < best) best = oth;
            }
            int buf = iter & 1;
            if (lane == 0) wred[buf][wid] = best;
            __syncthreads();

            unsigned long long tot = wred[buf][0];
            #pragma unroll
            for (int w = 1; w < NW; w++)
                if (wred[buf][w] < tot) tot = wred[buf][w];
            j1 = (int)(tot & 0xFFFFFFFFu);
            Sf = unorder_f((unsigned)(tot >> 32));

            int i0n = p[j1];
            if (i0n < 0) break;

            if ((j1 & (NTH - 1)) == tid) um |= (1u << (j1 >> 7));
            j0 = j1;
            i0 = i0n;
            shift = Sf;
            iter++;
        }

        // deferred dual updates
        #pragma unroll
        for (int k = 0; k < K_; k++) {
            int j = tid + k * NTH;
            if (j < Q_ && ((um >> k) & 1u)) {
                float diff = Sf - minv[k];
                vreg[k] -= diff;
                u[p[j]] += diff;
            }
        }
        if (tid == 0) u[i] += Sf;
        __syncthreads();

        if (tid == 0) {
            int j = j1;
            while (j != Q_) {
                int jn = sway[j];
                p[j] = (jn == Q_) ? i : p[jn];
                j = jn;
            }
        }
        __syncthreads();
    }

    // write indices sorted by query (rank via counting)
    for (int j = tid; j < Q_; j += NTH) {
        int r = p[j];
        if (r >= 0) colarr[r] = j;
    }
    __syncthreads();

    if (writeIdx) {
        float* oidx = out + (size_t)B_ * Q_ * T_;
        for (int t = tid; t < T_; t += NTH) {
            int c = colarr[t];
            int rank = 0;
            for (int s = 0; s < T_; s++) rank += (colarr[s] < c);
            oidx[(size_t)b * T_ + rank] = (float)c;                    // pred_idx
            oidx[(size_t)B_ * T_ + (size_t)b * T_ + rank] = (float)t;  // tgt_idx
        }
    }

    // reset rowmin identity for the next graph replay
    for (int t = tid; t < T_; t += NTH) g_rowmin[b * T_ + t] = 0ull;
}

// ---------------------------------------------------------------------------
extern "C" void kernel_launch(void* const* d_in, const int* in_sizes, int n_in,
                              void* d_out, int out_size) {
    const float* logits = (const float*)d_in[0];
    const float* pboxes = (const float*)d_in[1];
    const int*   labels = (const int*)d_in[2];
    const float* tboxes = (const float*)d_in[3];
    float* out = (float*)d_out;

    dim3 tg((Q_ + 31) / 32, B_);
    cost_fused_kernel<<<tg, NTC>>>(logits, pboxes, labels, tboxes, out);

    int writeIdx = (out_size >= (int)((long long)B_ * Q_ * T_ + 2LL * B_ * T_)) ? 1 : 0;
    hungarian_kernel<<<B_, NTH>>>(out, writeIdx);
}

// round 6
// speedup vs baseline: 1.3981x; 1.3981x over previous
#include <cuda_runtime.h>
#include <cstdint>

#define B_ 64
#define Q_ 900
#define T_ 100
#define C_ 256
#define NTC 256          // cost kernel block
#define NTH 512          // hungarian block
#define K_ 2             // columns per hungarian thread: NTH*K_ >= Q_
#define NW (NTH / 32)

// Scratch: transposed cost [B, T, Q] so hungarian reads contiguous rows.
__device__ float g_costT[(size_t)B_ * T_ * Q_];
// Per-(b,t) ~packed row-min key; 0 (static init) is the identity for atomicMax.
// real key = ~stored;  key = (order(cost) << 32) | q  -> max(~key) == min(key)
__device__ unsigned long long g_rowmin[B_ * T_];   // zero-initialized

__device__ __forceinline__ unsigned order_f(float f) {
    unsigned o = __float_as_uint(f);
    return (o & 0x80000000u) ? ~o : (o | 0x80000000u);
}
__device__ __forceinline__ float unorder_f(unsigned o) {
    return __uint_as_float((o & 0x80000000u) ? (o ^ 0x80000000u) : ~o);
}

// ---------------------------------------------------------------------------
// Kernel 1: one block per (b, 32-query tile). Label-sorted target order makes
// the logits gather semi-coalesced. Writes out[B,Q,T] and g_costT[B,T,Q]
// coalesced from the smem tile; folds per-target row-min into g_rowmin.
// (unchanged from R5 — measured ~7.5us)
// ---------------------------------------------------------------------------
__global__ void __launch_bounds__(NTC) cost_fused_kernel(
        const float* __restrict__ logits,
        const float* __restrict__ pboxes,
        const int* __restrict__ labels,
        const float* __restrict__ tboxes,
        float* __restrict__ out) {
    __shared__ int    lab_s[T_];
    __shared__ int    ord_s[T_];      // targets sorted by (label, t)
    __shared__ float4 tb_s[T_];
    __shared__ float4 pb_s[32];
    __shared__ float  tile[32][101];  // [q_in_tile][t]

    int b = blockIdx.y;
    int q0 = blockIdx.x * 32;
    int tid = threadIdx.x;

    if (tid < T_) {
        int lab = labels[b * T_ + tid];
        lab_s[tid] = lab;
        tb_s[tid] = __ldg(&((const float4*)tboxes)[b * T_ + tid]);
    }
    if (tid < 32 && q0 + tid < Q_)
        pb_s[tid] = __ldg(&((const float4*)pboxes)[b * Q_ + q0 + tid]);
    __syncthreads();

    if (tid < T_) {                   // rank sort by (label, index)
        int lab = lab_s[tid];
        int rank = 0;
        for (int s = 0; s < T_; s++) {
            int ls = lab_s[s];
            rank += (ls < lab) || (ls == lab && s < tid);
        }
        ord_s[rank] = tid;
    }
    __syncthreads();

    int qq = tid >> 3;                // 0..31
    int q = q0 + qq;
    int t_lo = tid & 7;               // 0..7
    if (q < Q_) {
        float4 pb = pb_s[qq];
        float ax0 = pb.x - 0.5f * pb.z, ay0 = pb.y - 0.5f * pb.w;
        float ax1 = pb.x + 0.5f * pb.z, ay1 = pb.y + 0.5f * pb.w;
        float areaA = (ax1 - ax0) * (ay1 - ay0);
        const float* lrow = logits + ((long long)b * Q_ + q) * C_;

        #pragma unroll
        for (int s = 0; s < 13; s++) {
            int sidx = t_lo + (s << 3);
            if (sidx >= T_) break;
            int tt = ord_s[sidx];     // label-sorted order -> coalesced gather

            float cc = -__ldg(lrow + lab_s[tt]);
            float4 tb = tb_s[tt];

            float cb = fabsf(pb.x - tb.x) + fabsf(pb.y - tb.y);
            cb += fabsf(pb.z - tb.z);
            cb += fabsf(pb.w - tb.w);

            float bx0 = tb.x - 0.5f * tb.z, by0 = tb.y - 0.5f * tb.w;
            float bx1 = tb.x + 0.5f * tb.z, by1 = tb.y + 0.5f * tb.w;

            float areaB = (bx1 - bx0) * (by1 - by0);
            float wx = fminf(ax1, bx1) - fmaxf(ax0, bx0); wx = fmaxf(wx, 0.f);
            float wy = fminf(ay1, by1) - fmaxf(ay0, by0); wy = fmaxf(wy, 0.f);
            float inter = wx * wy;
            float uni = areaA + areaB - inter;
            float iou = inter / uni;
            float ex = fmaxf(ax1, bx1) - fminf(ax0, bx0); ex = fmaxf(ex, 0.f);
            float ey = fmaxf(ay1, by1) - fminf(ay0, by0); ey = fmaxf(ey, 0.f);
            float enc = ex * ey;
            float giou = iou - (enc - uni) / enc;

            tile[qq][tt] = (cc + cb) - giou;
        }
    }
    __syncthreads();

    // out[B,Q,T]: coalesced (t fast) from smem
    for (int idx = tid; idx < 32 * T_; idx += NTC) {
        int qq2 = idx / T_, tt = idx - qq2 * T_;
        int q2 = q0 + qq2;
        if (q2 < Q_)
            out[((size_t)b * Q_ + q2) * T_ + tt] = tile[qq2][tt];
    }
    // costT[B,T,Q]: coalesced (q fast)
    for (int idx = tid; idx < 32 * T_; idx += NTC) {
        int tt = idx >> 5, q2 = q0 + (idx & 31);
        if (q2 < Q_)
            g_costT[((size_t)b * T_ + tt) * Q_ + q2] = tile[idx & 31][tt];
    }
    // per-target min over this block's queries -> atomicMax of ~key
    if (tid < T_) {
        unsigned long long best = ~0ull;
        int qmax = min(32, Q_ - q0);
        for (int k = 0; k < qmax; k++) {
            unsigned long long key =
                ((unsigned long long)order_f(tile[k][tid]) << 32) | (unsigned)(q0 + k);
            if (key < best) best = key;
        }
        atomicMax(&g_rowmin[b * T_ + tid], ~best);
    }
}

// ---------------------------------------------------------------------------
// Kernel 2: JV, greedy init from precomputed row-mins + deferred-dual SAP.
// One CTA (512 threads, K=2 cols/thread) per batch. REDUX-based argmin.
// ---------------------------------------------------------------------------
__global__ void __launch_bounds__(NTH) hungarian_kernel(float* __restrict__ out,
                                                        int writeIdx) {
    int b = blockIdx.x;
    const float* cost = g_costT + (size_t)b * T_ * Q_;

    __shared__ float u[T_ + 1];
    __shared__ int p[Q_];                 // row matched to col j (-1 free)
    __shared__ int sway[Q_];              // predecessor column
    __shared__ unsigned long long wred[2][NW];
    __shared__ int colarr[T_];
    __shared__ int argj[T_];
    __shared__ int matched[T_];

    int tid = threadIdx.x;
    int lane = tid & 31, wid = tid >> 5;

    float vreg[K_];
    float minv[K_];
    #pragma unroll
    for (int k = 0; k < K_; k++) vreg[k] = 0.f;

    for (int j = tid; j < Q_; j += NTH) p[j] = -1;
    if (tid == 0) u[T_] = 0.f;

    // ---- Phase 0: greedy duals from precomputed row-mins ----
    if (tid < T_) {
        unsigned long long key = ~g_rowmin[b * T_ + tid];
        argj[tid] = (int)(key & 0xFFFFFFFFu);
        u[tid] = unorder_f((unsigned)(key >> 32));
    }
    __syncthreads();

    if (tid == 0) {
        for (int i = 0; i < T_; i++) {
            int j = argj[i];
            if (p[j] < 0) { p[j] = i; matched[i] = 1; }
            else matched[i] = 0;
        }
    }
    __syncthreads();

    // ---- Phase 1: shortest augmenting path for each unmatched row ----
    for (int i = 0; i < T_; i++) {
        if (matched[i]) continue;

        unsigned um = 0;
        #pragma unroll
        for (int k = 0; k < K_; k++) {
            minv[k] = 1e30f;
            if (tid + k * NTH >= Q_) um |= (1u << k);
        }

        int j0 = Q_;
        int i0 = i;
        float shift = 0.f;
        int iter = 0;
        int j1;
        float Sf;

        while (true) {
            float base = shift - u[i0];
            const float* row = cost + (size_t)i0 * Q_;

            // per-thread best over its K_ columns (lowest-j tiebreak: k=0 first)
            unsigned bo = 0xFFFFFFFFu;     // ordered value (all-ones = +inf/invalid)
            unsigned bj = 0xFFFFFFFFu;
            #pragma unroll
            for (int k = 0; k < K_; k++) {
                int j = tid + k * NTH;
                if (!((um >> k) & 1u)) {
                    float cur = __ldg(row + j) - vreg[k] + base;
                    if (cur < minv[k]) { minv[k] = cur; sway[j] = j0; }
                    unsigned o = order_f(minv[k]);
                    if (o < bo) { bo = o; bj = (unsigned)j; }
                }
            }
            // warp argmin via 2x REDUX (exact lowest-index tiebreak)
            unsigned m = __reduce_min_sync(0xFFFFFFFFu, bo);
            unsigned jc = (bo == m) ? bj : 0xFFFFFFFFu;
            unsigned jm = __reduce_min_sync(0xFFFFFFFFu, jc);

            int buf = iter & 1;
            if (lane == 0)
                wred[buf][wid] = ((unsigned long long)m << 32) | jm;
            __syncthreads();

            unsigned long long tot = wred[buf][0];
            #pragma unroll
            for (int w = 1; w < NW; w++) {
                unsigned long long x = wred[buf][w];
                if (x < tot) tot = x;
            }
            j1 = (int)(tot & 0xFFFFFFFFu);
            Sf = unorder_f((unsigned)(tot >> 32));

            int i0n = p[j1];
            if (i0n < 0) break;

            if ((j1 & (NTH - 1)) == tid) um |= (1u << (j1 / NTH));
            j0 = j1;
            i0 = i0n;
            shift = Sf;
            iter++;
        }

        // deferred dual updates
        #pragma unroll
        for (int k = 0; k < K_; k++) {
            int j = tid + k * NTH;
            if (j < Q_ && ((um >> k) & 1u)) {
                float diff = Sf - minv[k];
                vreg[k] -= diff;
                u[p[j]] += diff;
            }
        }
        if (tid == 0) u[i] += Sf;
        __syncthreads();

        if (tid == 0) {
            int j = j1;
            while (j != Q_) {
                int jn = sway[j];
                p[j] = (jn == Q_) ? i : p[jn];
                j = jn;
            }
        }
        __syncthreads();
    }

    // write indices sorted by query (rank via counting)
    for (int j = tid; j < Q_; j += NTH) {
        int r = p[j];
        if (r >= 0) colarr[r] = j;
    }
    __syncthreads();

    if (writeIdx) {
        float* oidx = out + (size_t)B_ * Q_ * T_;
        if (tid < T_) {
            int c = colarr[tid];
            int rank = 0;
            for (int s = 0; s < T_; s++) rank += (colarr[s] < c);
            oidx[(size_t)b * T_ + rank] = (float)c;                      // pred_idx
            oidx[(size_t)B_ * T_ + (size_t)b * T_ + rank] = (float)tid;  // tgt_idx
        }
    }

    // reset rowmin identity for the next graph replay
    if (tid < T_) g_rowmin[b * T_ + tid] = 0ull;
}

// ---------------------------------------------------------------------------
extern "C" void kernel_launch(void* const* d_in, const int* in_sizes, int n_in,
                              void* d_out, int out_size) {
    const float* logits = (const float*)d_in[0];
    const float* pboxes = (const float*)d_in[1];
    const int*   labels = (const int*)d_in[2];
    const float* tboxes = (const float*)d_in[3];
    float* out = (float*)d_out;

    dim3 tg((Q_ + 31) / 32, B_);
    cost_fused_kernel<<<tg, NTC>>>(logits, pboxes, labels, tboxes, out);

    int writeIdx = (out_size >= (int)((long long)B_ * Q_ * T_ + 2LL * B_ * T_)) ? 1 : 0;
    hungarian_kernel<<<B_, NTH>>>(out, writeIdx);
}